// round 2
// baseline (speedup 1.0000x reference)
#include <cuda_runtime.h>

// Problem constants
#define NB     8
#define C1     2048
#define HW     56
#define PLANE  (HW*HW)      // 3136
#define SR     60           // smem row stride (floats), multiple of 4 for aligned float4
#define SROWS  58           // 56 + halo
#define SPLANE (SROWS*SR)   // 3480 floats per plane
#define SMEM_BYTES (4*SPLANE*4)  // 55680 B

// 0 = index stored as int32 (JAX default, x64 disabled), 1 = genuine int64
__device__ int g_idx_is_i64;

__global__ void detect_index_dtype(const unsigned int* __restrict__ idx_words) {
    // If int64 layout: odd words (high halves) of first 32 entries are all 0.
    // If int32 layout: those words are index[1],[3],...,[63] — a permutation
    // contains the value 0 exactly once, so at least 31 of them are nonzero.
    if (threadIdx.x == 0) {
        int any_nonzero = 0;
        for (int k = 0; k < 32; k++) any_nonzero |= (idx_words[2*k + 1] != 0u);
        g_idx_is_i64 = !any_nonzero;
    }
}

// One block per (oc, n). Fused: depthwise conv3x3 on the 4 gathered source
// channels + running max, input planes staged in zero-padded shared memory.
__global__ __launch_bounds__(256)
void fused_conv_gather_max(const float* __restrict__ x,
                           const float* __restrict__ Wt,
                           const float* __restrict__ b1,
                           const int* __restrict__ index32,
                           float* __restrict__ out) {
    extern __shared__ float sm[];   // 4 planes of SROWS x SR
    const int oc  = blockIdx.x;
    const int n   = blockIdx.y;
    const int tid = threadIdx.x;
    const int is64 = g_idx_is_i64;

    // Resolve the 4 source channels and their input channels
    int c[4], ic[4];
#pragma unroll
    for (int g = 0; g < 4; g++) {
        int iv;
        if (is64) iv = (int)((const long long*)index32)[oc*4 + g];
        else      iv = index32[oc*4 + g];          // values in [0, 8192)
        c[g]  = iv & (C1 - 1);                     // iv % 2048
        ic[g] = c[g] >> 7;                         // 128 out-channels per input channel
    }

    // Zero only the border cells the conv will read:
    // rows {0,57} cols [0,58), and cols {0,57} rows [0,58). 232 cells/plane.
    for (int i = tid; i < 4*232; i += blockDim.x) {
        int g = i / 232;
        int j = i - g*232;
        int r, cl;
        if (j < 116) { r  = (j >= 58) ? 57 : 0; cl = j % 58; }
        else { int k = j - 116; cl = (k >= 58) ? 57 : 0; r = k % 58; }
        sm[g*SPLANE + r*SR + cl] = 0.0f;
    }

    // Stage interior: smem[(h+1)*SR + (w+1)] = x[n, ic, h, w]. Disjoint from
    // the border cells above, so one barrier suffices.
#pragma unroll
    for (int g = 0; g < 4; g++) {
        const float4* src = (const float4*)(x + (long)(n*16 + ic[g])*PLANE);
        float* dst = sm + g*SPLANE;
        for (int i = tid; i < PLANE/4; i += blockDim.x) {
            float4 v = src[i];
            int e = i * 4;
            int r = e / HW;
            int cp = e - r*HW;
            float* d = dst + (r+1)*SR + (cp+1);
            d[0] = v.x; d[1] = v.y; d[2] = v.z; d[3] = v.w;
        }
    }
    __syncthreads();

    // Block-uniform weights/biases into registers
    float wg[4][9], bs[4];
#pragma unroll
    for (int g = 0; g < 4; g++) {
#pragma unroll
        for (int k = 0; k < 9; k++) wg[g][k] = Wt[c[g]*9 + k];
        bs[g] = b1[c[g]];
    }

    float* outp = out + (long)(n*C1 + oc)*PLANE;

    // Each task = 4 horizontally consecutive output pixels (one float4 store).
    // 56 rows x 14 strips = 784 tasks.
    for (int s = tid; s < 784; s += blockDim.x) {
        int row = s / 14;
        int w0  = (s - row*14) * 4;
        float m0, m1, m2, m3;
#pragma unroll
        for (int g = 0; g < 4; g++) {
            float a0 = bs[g], a1 = bs[g], a2 = bs[g], a3 = bs[g];
            const float* base = sm + g*SPLANE + row*SR + w0;
#pragma unroll
            for (int r = 0; r < 3; r++) {
                float4 v = *(const float4*)(base + r*SR);      // cols w0..w0+3
                float2 u = *(const float2*)(base + r*SR + 4);  // cols w0+4..w0+5
                float k0 = wg[g][r*3+0], k1 = wg[g][r*3+1], k2 = wg[g][r*3+2];
                a0 = fmaf(k0, v.x, a0); a0 = fmaf(k1, v.y, a0); a0 = fmaf(k2, v.z, a0);
                a1 = fmaf(k0, v.y, a1); a1 = fmaf(k1, v.z, a1); a1 = fmaf(k2, v.w, a1);
                a2 = fmaf(k0, v.z, a2); a2 = fmaf(k1, v.w, a2); a2 = fmaf(k2, u.x, a2);
                a3 = fmaf(k0, v.w, a3); a3 = fmaf(k1, u.x, a3); a3 = fmaf(k2, u.y, a3);
            }
            if (g == 0) { m0 = a0; m1 = a1; m2 = a2; m3 = a3; }
            else {
                m0 = fmaxf(m0, a0); m1 = fmaxf(m1, a1);
                m2 = fmaxf(m2, a2); m3 = fmaxf(m3, a3);
            }
        }
        *(float4*)(outp + row*HW + w0) = make_float4(m0, m1, m2, m3);
    }
}

extern "C" void kernel_launch(void* const* d_in, const int* in_sizes, int n_in,
                              void* d_out, int out_size) {
    const float* x     = (const float*)d_in[0];
    const float* Wt    = (const float*)d_in[1];
    const float* b1    = (const float*)d_in[2];
    const int*   index = (const int*)d_in[3];
    float*       out   = (float*)d_out;

    cudaFuncSetAttribute(fused_conv_gather_max,
                         cudaFuncAttributeMaxDynamicSharedMemorySize, SMEM_BYTES);

    detect_index_dtype<<<1, 32>>>((const unsigned int*)index);

    dim3 grid(C1, NB);
    fused_conv_gather_max<<<grid, 256, SMEM_BYTES>>>(x, Wt, b1, index, out);
}

// round 4
// speedup vs baseline: 1.2604x; 1.2604x over previous
#include <cuda_runtime.h>
#include <float.h>

// Problem constants
#define NB     8
#define NC1    2048
#define HW     56
#define PLANE  (HW*HW)      // 3136
#define SR     60           // smem row stride (floats)
#define SPLANE (58*SR)      // 3480 floats per padded plane
#define SMEM_BYTES (4*SPLANE*4)  // 55680 B

// 0 = index stored as int32 (JAX default, x64 disabled), 1 = genuine int64
__device__ int g_idx_is_i64;

__global__ void detect_index_dtype(const unsigned int* __restrict__ idx_words) {
    // int64 layout: odd words (high halves) of first 32 entries are all 0.
    // int32 layout: those words are index[1],[3],...,[63] of a permutation of
    // [0,8192): at most one of them is zero.
    if (threadIdx.x == 0) {
        int any_nonzero = 0;
        for (int k = 0; k < 32; k++) any_nonzero |= (idx_words[2*k + 1] != 0u);
        g_idx_is_i64 = !any_nonzero;
    }
}

__global__ __launch_bounds__(256, 4)
void fused_conv_gather_max(const float* __restrict__ x,
                           const float* __restrict__ Wt,
                           const float* __restrict__ b1,
                           const int* __restrict__ index32,
                           float* __restrict__ out) {
    extern __shared__ float sm[];   // 4 padded planes of 58 x 60
    const int oc  = blockIdx.x;
    const int n   = blockIdx.y;
    const int tid = threadIdx.x;
    const int is64 = g_idx_is_i64;

    // Resolve the 4 source channels and their input channels
    int c[4], ic[4];
#pragma unroll
    for (int g = 0; g < 4; g++) {
        int iv;
        if (is64) iv = (int)((const long long*)index32)[oc*4 + g];
        else      iv = index32[oc*4 + g];
        c[g]  = iv & (NC1 - 1);
        ic[g] = c[g] >> 7;     // 128 out-channels per input channel
    }

    // ---- Staging: aligned STS.128 via half-warp shuffle ------------------
    // Padded layout: sm_plane[r+1][col+1] = x[r][col]; float4 group hl of a
    // padded row = {in[4hl-1], in[4hl], in[4hl+1], in[4hl+2]}.
    const int warp = tid >> 5, lane = tid & 31;
    const int half = lane >> 4, hl = lane & 15;
#pragma unroll 1
    for (int g = 0; g < 4; g++) {
        const float* src = x + (long)(n*16 + ic[g])*PLANE;
        float* pb = sm + g*SPLANE;
#pragma unroll 1
        for (int r = warp*2 + half; r < HW; r += 16) {
            float4 v = make_float4(0.f, 0.f, 0.f, 0.f);
            if (hl < 14) v = ((const float4*)(src + r*HW))[hl];
            float pw = __shfl_up_sync(0xffffffffu, v.w, 1, 16);
            float4 o = make_float4(hl ? pw : 0.f, v.x, v.y, v.z);
            if (hl < 15) ((float4*)(pb + (r+1)*SR))[hl] = o;  // aligned
        }
    }
    // Zero padded rows 0 and 57 of each plane (15 float4 per row)
    for (int i = tid; i < 4*2*15; i += 256) {
        int g = i / 30, j = i - g*30;
        int r = (j < 15) ? 0 : 57;
        int q = j % 15;
        ((float4*)(sm + g*SPLANE + r*SR))[q] = make_float4(0.f, 0.f, 0.f, 0.f);
    }
    __syncthreads();

    // ---- Per-thread vertical run of 4-wide strips ------------------------
    // 784 strips ordered column-major: id = sx*56 + row.
    // Threads 0..15 take 4 strips, 16..255 take 3. Consecutive rows in a run
    // share the sliding 3-row window.
    const int L     = (tid < 16) ? 4 : 3;
    const int start = tid*3 + min(tid, 16);
    int sx_[4], row_[4];
#pragma unroll
    for (int i = 0; i < 4; i++) {
        int id = min(start + i, 783);
        sx_[i]  = id / 56;
        row_[i] = id - 56*sx_[i];
    }

    float4 acc[4];
#pragma unroll
    for (int i = 0; i < 4; i++)
        acc[i] = make_float4(-FLT_MAX, -FLT_MAX, -FLT_MAX, -FLT_MAX);

#pragma unroll 1
    for (int g = 0; g < 4; g++) {
        const float* pl = sm + g*SPLANE;
        const float* wp = Wt + c[g]*9;
        const float k0 = __ldg(wp+0), k1 = __ldg(wp+1), k2 = __ldg(wp+2);
        const float k3 = __ldg(wp+3), k4 = __ldg(wp+4), k5 = __ldg(wp+5);
        const float k6 = __ldg(wp+6), k7 = __ldg(wp+7), k8 = __ldg(wp+8);
        const float bb = __ldg(b1 + c[g]);

        float4 rA, rB, rC; float2 tA, tB, tC;
#pragma unroll
        for (int i = 0; i < 4; i++) {
            if (i < L) {
                const float* base = pl + row_[i]*SR + sx_[i]*4;
                if (i == 0 || row_[i] == 0) {
                    rA = *(const float4*)(base);        tA = *(const float2*)(base + 4);
                    rB = *(const float4*)(base + SR);   tB = *(const float2*)(base + SR + 4);
                } else {
                    rA = rB; tA = tB; rB = rC; tB = tC;
                }
                rC = *(const float4*)(base + 2*SR); tC = *(const float2*)(base + 2*SR + 4);

                float a0 = bb, a1 = bb, a2 = bb, a3 = bb;
                a0 = fmaf(k0,rA.x,a0); a0 = fmaf(k1,rA.y,a0); a0 = fmaf(k2,rA.z,a0);
                a1 = fmaf(k0,rA.y,a1); a1 = fmaf(k1,rA.z,a1); a1 = fmaf(k2,rA.w,a1);
                a2 = fmaf(k0,rA.z,a2); a2 = fmaf(k1,rA.w,a2); a2 = fmaf(k2,tA.x,a2);
                a3 = fmaf(k0,rA.w,a3); a3 = fmaf(k1,tA.x,a3); a3 = fmaf(k2,tA.y,a3);

                a0 = fmaf(k3,rB.x,a0); a0 = fmaf(k4,rB.y,a0); a0 = fmaf(k5,rB.z,a0);
                a1 = fmaf(k3,rB.y,a1); a1 = fmaf(k4,rB.z,a1); a1 = fmaf(k5,rB.w,a1);
                a2 = fmaf(k3,rB.z,a2); a2 = fmaf(k4,rB.w,a2); a2 = fmaf(k5,tB.x,a2);
                a3 = fmaf(k3,rB.w,a3); a3 = fmaf(k4,tB.x,a3); a3 = fmaf(k5,tB.y,a3);

                a0 = fmaf(k6,rC.x,a0); a0 = fmaf(k7,rC.y,a0); a0 = fmaf(k8,rC.z,a0);
                a1 = fmaf(k6,rC.y,a1); a1 = fmaf(k7,rC.z,a1); a1 = fmaf(k8,rC.w,a1);
                a2 = fmaf(k6,rC.z,a2); a2 = fmaf(k7,rC.w,a2); a2 = fmaf(k8,tC.x,a2);
                a3 = fmaf(k6,rC.w,a3); a3 = fmaf(k7,tC.x,a3); a3 = fmaf(k8,tC.y,a3);

                acc[i].x = fmaxf(acc[i].x, a0);
                acc[i].y = fmaxf(acc[i].y, a1);
                acc[i].z = fmaxf(acc[i].z, a2);
                acc[i].w = fmaxf(acc[i].w, a3);
            }
        }
    }

    // ---- Coalesced output via smem bounce --------------------------------
    __syncthreads();   // all plane reads done; reuse smem for results
#pragma unroll
    for (int i = 0; i < 4; i++) {
        if (i < L) ((float4*)sm)[row_[i]*14 + sx_[i]] = acc[i];
    }
    __syncthreads();
    float* outp = out + (long)(n*NC1 + oc)*PLANE;
    for (int i = tid; i < 784; i += 256)
        ((float4*)outp)[i] = ((const float4*)sm)[i];
}

extern "C" void kernel_launch(void* const* d_in, const int* in_sizes, int n_in,
                              void* d_out, int out_size) {
    const float* x     = (const float*)d_in[0];
    const float* Wt    = (const float*)d_in[1];
    const float* b1    = (const float*)d_in[2];
    const int*   index = (const int*)d_in[3];
    float*       out   = (float*)d_out;

    cudaFuncSetAttribute(fused_conv_gather_max,
                         cudaFuncAttributeMaxDynamicSharedMemorySize, SMEM_BYTES);

    detect_index_dtype<<<1, 32>>>((const unsigned int*)index);

    dim3 grid(NC1, NB);
    fused_conv_gather_max<<<grid, 256, SMEM_BYTES>>>(x, Wt, b1, index, out);
}

// round 7
// speedup vs baseline: 3.0492x; 2.4192x over previous
#include <cuda_runtime.h>
#include <float.h>

// Problem constants
#define NB     8
#define NC1    2048
#define HW     56
#define PLANE  (HW*HW)          // 3136
#define SR     60               // smem row stride (floats)
#define SPLANE (58*SR)          // 3480 floats per padded plane
#define NPLANES 16
#define SMEM_BYTES (NPLANES*SPLANE*4)   // 222720 B
#define OC_PER_BLK 128
#define NTASKS (OC_PER_BLK*14)  // 1792
#define NTHREADS 512

// 0 = index stored as int32 (JAX default, x64 disabled), 1 = genuine int64
__device__ int g_idx_is_i64;

__global__ void detect_index_dtype(const unsigned int* __restrict__ idx_words) {
    // int64 layout: odd words (high halves) of first 32 entries are all 0.
    // int32 layout: those words are index[1],[3],...,[63] of a permutation of
    // [0,8192): at most one of them is zero.
    if (threadIdx.x == 0) {
        int any_nonzero = 0;
        for (int k = 0; k < 32; k++) any_nonzero |= (idx_words[2*k + 1] != 0u);
        g_idx_is_i64 = !any_nonzero;
    }
}

__global__ __launch_bounds__(NTHREADS)
void fused_conv_gather_max(const float* __restrict__ x,
                           const float* __restrict__ Wt,
                           const float* __restrict__ b1,
                           const int* __restrict__ index32,
                           float* __restrict__ out) {
    extern __shared__ float sm[];   // 16 padded planes of 58 x 60
    const int ocg = blockIdx.x;     // oc group (0..15)
    const int n   = blockIdx.y;
    const int tid = threadIdx.x;
    const int is64 = g_idx_is_i64;

    // ---- Stage all 16 input planes once (aligned STS.128 via shuffle) ----
    // Padded: plane[r+1][c+1] = x[r][c]; float4 group hl of a padded row is
    // {in[4hl-1], in[4hl], in[4hl+1], in[4hl+2]}.
    const int grp = tid >> 4;       // 0..31 (16-lane groups)
    const int hl  = tid & 15;
#pragma unroll 1
    for (int g = 0; g < NPLANES; g++) {
        const float* src = x + (long)(n*NPLANES + g)*PLANE;
        float* pb = sm + g*SPLANE;
#pragma unroll 1
        for (int r = grp; r < HW; r += 32) {
            float4 v = make_float4(0.f, 0.f, 0.f, 0.f);
            if (hl < 14) v = ((const float4*)(src + r*HW))[hl];
            float pw = __shfl_up_sync(0xffffffffu, v.w, 1, 16);
            float4 o = make_float4(hl ? pw : 0.f, v.x, v.y, v.z);
            if (hl < 15) ((float4*)(pb + (r+1)*SR))[hl] = o;   // aligned STS.128
        }
    }
    // Zero padded bottom row 57 of each plane (row 0 is never read: the
    // partial-sum init below accounts for it). 16 planes x 15 float4.
    if (tid < NPLANES*15) {
        int g = tid / 15, q = tid - g*15;
        ((float4*)(sm + g*SPLANE + 57*SR))[q] = make_float4(0.f, 0.f, 0.f, 0.f);
    }
    __syncthreads();

    // ---- Tasks: (oc_local, sx) columns; thread scans all rows once -------
#pragma unroll 1
    for (int t = tid; t < NTASKS; t += NTHREADS) {
        const int ocl = t / 14;
        const int sx  = t - ocl*14;
        const int oc  = ocg*OC_PER_BLK + ocl;

        // Resolve 4 source channels; load weights/bias
        float k[4][9], bs[4];
        const float* base[4];
#pragma unroll
        for (int g = 0; g < 4; g++) {
            int iv;
            if (is64) iv = (int)((const long long*)index32)[oc*4 + g];
            else      iv = index32[oc*4 + g];
            int c  = iv & (NC1 - 1);
            int ic = c >> 7;                 // 128 out-channels per input chan
            base[g] = sm + ic*SPLANE + sx*4;
            const float* wp = Wt + c*9;
#pragma unroll
            for (int j = 0; j < 9; j++) k[g][j] = __ldg(wp + j);
            bs[g] = __ldg(b1 + c);
        }

        // Partial-row accumulators per channel:
        //  p1[g][j] = bias + top-taps of the next output row
        //  p0[g][j] = p1 + mid-taps (completed by bot-taps of row rr)
        float p0[4][4], p1[4][4];
#pragma unroll
        for (int g = 0; g < 4; g++)
#pragma unroll
            for (int j = 0; j < 4; j++) { p0[g][j] = bs[g]; p1[g][j] = bs[g]; }

        float* outp = out + ((long)(n*NC1 + oc))*PLANE + sx*4;

#pragma unroll 1
        for (int rr = 1; rr <= 57; rr++) {
            float m[4];
#pragma unroll
            for (int g = 0; g < 4; g++) {
                const float* rp = base[g] + rr*SR;
                float4 a = *(const float4*)rp;
                float2 bq = *(const float2*)(rp + 4);
                float v0 = a.x, v1 = a.y, v2 = a.z, v3 = a.w, v4 = bq.x, v5 = bq.y;
                const float k0 = k[g][0], k1 = k[g][1], k2 = k[g][2];
                const float k3 = k[g][3], k4 = k[g][4], k5 = k[g][5];
                const float k6 = k[g][6], k7 = k[g][7], k8 = k[g][8];
                const float bb = bs[g];
#pragma unroll
                for (int j = 0; j < 4; j++) {
                    float w0 = (j==0)?v0:(j==1)?v1:(j==2)?v2:v3;
                    float w1 = (j==0)?v1:(j==1)?v2:(j==2)?v3:v4;
                    float w2 = (j==0)?v2:(j==1)?v3:(j==2)?v4:v5;
                    float c0 = fmaf(k8, w2, fmaf(k7, w1, fmaf(k6, w0, p0[g][j])));
                    m[j] = g ? fmaxf(m[j], c0) : c0;
                    p0[g][j] = fmaf(k5, w2, fmaf(k4, w1, fmaf(k3, w0, p1[g][j])));
                    p1[g][j] = fmaf(k2, w2, fmaf(k1, w1, fmaf(k0, w0, bb)));
                }
            }
            if (rr >= 2)
                *(float4*)(outp + (rr-2)*HW) = make_float4(m[0], m[1], m[2], m[3]);
        }
    }
}

extern "C" void kernel_launch(void* const* d_in, const int* in_sizes, int n_in,
                              void* d_out, int out_size) {
    const float* x     = (const float*)d_in[0];
    const float* Wt    = (const float*)d_in[1];
    const float* b1    = (const float*)d_in[2];
    const int*   index = (const int*)d_in[3];
    float*       out   = (float*)d_out;

    cudaFuncSetAttribute(fused_conv_gather_max,
                         cudaFuncAttributeMaxDynamicSharedMemorySize, SMEM_BYTES);

    detect_index_dtype<<<1, 32>>>((const unsigned int*)index);

    dim3 grid(NC1/OC_PER_BLK, NB);   // 16 x 8 = 128 blocks
    fused_conv_gather_max<<<grid, NTHREADS, SMEM_BYTES>>>(x, Wt, b1, index, out);
}